// round 3
// baseline (speedup 1.0000x reference)
#include <cuda_runtime.h>
#include <cstdint>

// ============================================================================
// ResGatedGraphConv x3 + softmax.
//   per layer: k = x@kw+kb ; q = x@qw+qb ; v = x@vw+vb ; skip = x@sw + bias
//              eta = sigmoid(k[dst] + q[src]); H[dst] += eta * v[src]  (H init = skip)
//   final: softmax over 64 cols.
// ============================================================================

#define NMAX 20000
#define BM 128
#define BN 64
#define BK 16
#define TM 8
#define TN 4

// scratch (device globals: no allocation allowed)
__device__ float g_K [NMAX * 256];
__device__ float g_Q [NMAX * 256];
__device__ float g_V [NMAX * 256];
__device__ float g_Ha[NMAX * 256];
__device__ float g_Hb[NMAX * 256];
__device__ int   g_is64;

// ----------------------------------------------------------------------------
// edge_index dtype detection: if stored as int64, the high 32-bit words of the
// first 2048 entries are all zero (node ids < 2^31). If int32, those words are
// random node ids -> virtually impossible to all be zero.
// ----------------------------------------------------------------------------
__global__ void detect_i64(const unsigned int* __restrict__ p) {
    __shared__ unsigned int s;
    if (threadIdx.x == 0) s = 0u;
    __syncthreads();
    unsigned int v = 0u;
    for (int i = threadIdx.x; i < 2048; i += blockDim.x) v |= p[2 * i + 1];
    atomicOr(&s, v);
    __syncthreads();
    if (threadIdx.x == 0) g_is64 = (s == 0u) ? 1 : 0;
}

// ----------------------------------------------------------------------------
// Tiled fp32 GEMM: C[M,Nc] = A[M,K] @ W[K,Nc] + bias[Nc]
// 256 threads, 128x64 block tile, 8x4 per-thread microtile.
// Requires K % 16 == 0, Nc % 64 == 0 (true for 256/128/64).
// ----------------------------------------------------------------------------
__global__ __launch_bounds__(256, 2) void gemm_bias(
    const float* __restrict__ A, const float* __restrict__ W,
    const float* __restrict__ bias, float* __restrict__ C,
    int M, int K, int Nc)
{
    __shared__ float As[BK][BM + 4];
    __shared__ float Bs[BK][BN];

    const int tid = threadIdx.x;
    const int tx  = tid & 15;          // 0..15  -> column group (4 cols)
    const int ty  = tid >> 4;          // 0..15  -> row group (8 rows)
    const int rowBase = blockIdx.y * BM;
    const int colBase = blockIdx.x * BN;

    float acc[TM][TN];
#pragma unroll
    for (int i = 0; i < TM; i++)
#pragma unroll
        for (int j = 0; j < TN; j++) acc[i][j] = 0.f;

    // A-tile load mapping: each thread loads 2 float4 (row-major, 4 float4 per row)
    const int a_k4  = (tid & 3) * 4;   // k offset within tile
    const int a_row = tid >> 2;        // 0..63 (+64 on 2nd iter)
    // B-tile load mapping: each thread loads 1 float4
    const int b_c4  = (tid & 15) * 4;
    const int b_k   = tid >> 4;        // 0..15

    for (int kk = 0; kk < K; kk += BK) {
#pragma unroll
        for (int it = 0; it < 2; it++) {
            int r = a_row + it * 64;
            int grow = rowBase + r;
            float4 av = make_float4(0.f, 0.f, 0.f, 0.f);
            if (grow < M)
                av = *(const float4*)&A[(size_t)grow * K + kk + a_k4];
            As[a_k4 + 0][r] = av.x;
            As[a_k4 + 1][r] = av.y;
            As[a_k4 + 2][r] = av.z;
            As[a_k4 + 3][r] = av.w;
        }
        {
            float4 bv = *(const float4*)&W[(size_t)(kk + b_k) * Nc + colBase + b_c4];
            *(float4*)&Bs[b_k][b_c4] = bv;
        }
        __syncthreads();

#pragma unroll
        for (int k = 0; k < BK; k++) {
            float4 b = *(const float4*)&Bs[k][tx * TN];
            float a[TM];
#pragma unroll
            for (int i = 0; i < TM; i++) a[i] = As[k][ty * TM + i];
#pragma unroll
            for (int i = 0; i < TM; i++) {
                acc[i][0] = fmaf(a[i], b.x, acc[i][0]);
                acc[i][1] = fmaf(a[i], b.y, acc[i][1]);
                acc[i][2] = fmaf(a[i], b.z, acc[i][2]);
                acc[i][3] = fmaf(a[i], b.w, acc[i][3]);
            }
        }
        __syncthreads();
    }

    float4 bv = *(const float4*)&bias[colBase + tx * TN];
#pragma unroll
    for (int i = 0; i < TM; i++) {
        int grow = rowBase + ty * TM + i;
        if (grow < M) {
            float4 o;
            o.x = acc[i][0] + bv.x;
            o.y = acc[i][1] + bv.y;
            o.z = acc[i][2] + bv.z;
            o.w = acc[i][3] + bv.w;
            *(float4*)&C[(size_t)grow * Nc + colBase + tx * TN] = o;
        }
    }
}

// ----------------------------------------------------------------------------
// Edge kernel: per (edge, 4-feature chunk):
//   m = sigmoid(K[dst] + Q[src]) * V[src];  H[dst] += m  (vector red, no return)
// chunks per edge = D/4 = 1<<cshift. Consecutive threads cover one edge's row
// -> gather loads are coalesced; dst rows are random but live in L2.
// ----------------------------------------------------------------------------
__global__ void edge_gate(const void* __restrict__ ei_raw,
                          const float* __restrict__ Kb,
                          const float* __restrict__ Qb,
                          const float* __restrict__ Vb,
                          float* __restrict__ H,
                          int E, int D, int cshift)
{
    long long idx = (long long)blockIdx.x * blockDim.x + threadIdx.x;
    long long total = (long long)E << cshift;
    if (idx >= total) return;
    int e = (int)(idx >> cshift);
    int c = ((int)idx & ((1 << cshift) - 1)) << 2;

    int src, dst;
    if (g_is64) {
        const long long* ei = (const long long*)ei_raw;
        src = (int)ei[e];
        dst = (int)ei[E + e];
    } else {
        const int* ei = (const int*)ei_raw;
        src = ei[e];
        dst = ei[E + e];
    }

    const float4 k = *(const float4*)&Kb[(size_t)dst * D + c];
    const float4 q = *(const float4*)&Qb[(size_t)src * D + c];
    const float4 v = *(const float4*)&Vb[(size_t)src * D + c];

    float4 m;
    m.x = v.x / (1.f + __expf(-(k.x + q.x)));
    m.y = v.y / (1.f + __expf(-(k.y + q.y)));
    m.z = v.z / (1.f + __expf(-(k.z + q.z)));
    m.w = v.w / (1.f + __expf(-(k.w + q.w)));

    float* addr = &H[(size_t)dst * D + c];
    asm volatile("red.global.add.v4.f32 [%0], {%1,%2,%3,%4};"
                 :: "l"(addr), "f"(m.x), "f"(m.y), "f"(m.z), "f"(m.w)
                 : "memory");
}

// ----------------------------------------------------------------------------
// Row softmax over 64 columns: one warp per row, 2 elems per lane.
// ----------------------------------------------------------------------------
__global__ void softmax64(const float* __restrict__ H, float* __restrict__ out, int M)
{
    int warp = threadIdx.x >> 5;
    int lane = threadIdx.x & 31;
    int row  = blockIdx.x * (blockDim.x >> 5) + warp;
    if (row >= M) return;
    float a = H[row * 64 + lane];
    float b = H[row * 64 + 32 + lane];
    float mx = fmaxf(a, b);
#pragma unroll
    for (int o = 16; o > 0; o >>= 1) mx = fmaxf(mx, __shfl_xor_sync(0xffffffffu, mx, o));
    float ea = __expf(a - mx);
    float eb = __expf(b - mx);
    float s  = ea + eb;
#pragma unroll
    for (int o = 16; o > 0; o >>= 1) s += __shfl_xor_sync(0xffffffffu, s, o);
    float inv = 1.f / s;
    out[row * 64 + lane]      = ea * inv;
    out[row * 64 + 32 + lane] = eb * inv;
}

// ----------------------------------------------------------------------------
extern "C" void kernel_launch(void* const* d_in, const int* in_sizes, int n_in,
                              void* d_out, int out_size)
{
    const float* x  = (const float*)d_in[0];
    const void*  ei = d_in[1];
    const int Nn = in_sizes[0] / 256;
    const int E  = in_sizes[1] / 2;

    float *pK, *pQ, *pV, *pHa, *pHb;
    cudaGetSymbolAddress((void**)&pK,  g_K);
    cudaGetSymbolAddress((void**)&pQ,  g_Q);
    cudaGetSymbolAddress((void**)&pV,  g_V);
    cudaGetSymbolAddress((void**)&pHa, g_Ha);
    cudaGetSymbolAddress((void**)&pHb, g_Hb);

    const float* w[26];
    for (int i = 2; i < 26; i++) w[i] = (const float*)d_in[i];

    dim3 blk(256);
    const int gy = (Nn + BM - 1) / BM;

    detect_i64<<<1, 256>>>((const unsigned int*)ei);

    // ---- layer 1: din=256, dout=256, input x, output pHa ----
    {
        dim3 grid(256 / BN, gy);
        gemm_bias<<<grid, blk>>>(x, w[2],  w[3],  pK,  Nn, 256, 256);
        gemm_bias<<<grid, blk>>>(x, w[4],  w[5],  pQ,  Nn, 256, 256);
        gemm_bias<<<grid, blk>>>(x, w[6],  w[7],  pV,  Nn, 256, 256);
        gemm_bias<<<grid, blk>>>(x, w[20], w[21], pHa, Nn, 256, 256);
        long long tot = (long long)E * 64;
        edge_gate<<<(unsigned)((tot + 255) / 256), blk>>>(ei, pK, pQ, pV, pHa, E, 256, 6);
    }
    // ---- layer 2: din=256, dout=128, input pHa, output pHb ----
    {
        dim3 grid(128 / BN, gy);
        gemm_bias<<<grid, blk>>>(pHa, w[8],  w[9],  pK,  Nn, 256, 128);
        gemm_bias<<<grid, blk>>>(pHa, w[10], w[11], pQ,  Nn, 256, 128);
        gemm_bias<<<grid, blk>>>(pHa, w[12], w[13], pV,  Nn, 256, 128);
        gemm_bias<<<grid, blk>>>(pHa, w[22], w[23], pHb, Nn, 256, 128);
        long long tot = (long long)E * 32;
        edge_gate<<<(unsigned)((tot + 255) / 256), blk>>>(ei, pK, pQ, pV, pHb, E, 128, 5);
    }
    // ---- layer 3: din=128, dout=64, input pHb, output pHa ----
    {
        dim3 grid(64 / BN, gy);
        gemm_bias<<<grid, blk>>>(pHb, w[14], w[15], pK,  Nn, 128, 64);
        gemm_bias<<<grid, blk>>>(pHb, w[16], w[17], pQ,  Nn, 128, 64);
        gemm_bias<<<grid, blk>>>(pHb, w[18], w[19], pV,  Nn, 128, 64);
        gemm_bias<<<grid, blk>>>(pHb, w[24], w[25], pHa, Nn, 128, 64);
        long long tot = (long long)E * 16;
        edge_gate<<<(unsigned)((tot + 255) / 256), blk>>>(ei, pK, pQ, pV, pHa, E, 64, 4);
        softmax64<<<(Nn + 7) / 8, 256>>>(pHa, (float*)d_out, Nn);
    }
}

// round 6
// speedup vs baseline: 1.1533x; 1.1533x over previous
#include <cuda_runtime.h>
#include <cstdint>

// ============================================================================
// ResGatedGraphConv x3 + softmax.
//   per layer: k = x@kw+kb ; q = x@qw+qb ; v = x@vw+vb ; skip = x@sw + bias
//              eta = sigmoid(k[dst] + q[src]); H[dst] += eta * v[src]  (H init = skip)
//   final: softmax over 64 cols.
// ============================================================================

#define NMAX 20000

// scratch (device globals: no allocation allowed)
__device__ float g_K [NMAX * 256];
__device__ float g_Q [NMAX * 256];
__device__ float g_V [NMAX * 256];
__device__ float g_Ha[NMAX * 256];
__device__ float g_Hb[NMAX * 256];
__device__ int   g_is64;

// ----------------------------------------------------------------------------
// edge_index dtype detection: if stored as int64, the high 32-bit words of the
// first 2048 entries are all zero (node ids < 2^31).
// ----------------------------------------------------------------------------
__global__ void detect_i64(const unsigned int* __restrict__ p) {
    __shared__ unsigned int s;
    if (threadIdx.x == 0) s = 0u;
    __syncthreads();
    unsigned int v = 0u;
    for (int i = threadIdx.x; i < 2048; i += blockDim.x) v |= p[2 * i + 1];
    atomicOr(&s, v);
    __syncthreads();
    if (threadIdx.x == 0) g_is64 = (s == 0u) ? 1 : 0;
}

// ----------------------------------------------------------------------------
// Fused 4-way tiled fp32 GEMM: C_z[M,Nc] = A[M,K] @ W_z[K,Nc] + bias_z
// blockIdx.z in 0..3 selects (W, bias, C). 256 threads, BMx BN block tile,
// 8 x (BN/16) per-thread microtile, double-buffered smem with reg prefetch.
// Requires K % 16 == 0, Nc % BN == 0.
// ----------------------------------------------------------------------------
template<int BN>
__global__ __launch_bounds__(256, 2) void gemm4(
    const float* __restrict__ A,
    const float* __restrict__ W0, const float* __restrict__ W1,
    const float* __restrict__ W2, const float* __restrict__ W3,
    const float* __restrict__ b0, const float* __restrict__ b1,
    const float* __restrict__ b2, const float* __restrict__ b3,
    float* __restrict__ C0, float* __restrict__ C1,
    float* __restrict__ C2, float* __restrict__ C3,
    int M, int K, int Nc)
{
    constexpr int BM = 128;
    constexpr int BK = 16;
    constexpr int TM = 8;
    constexpr int TN = BN / 16;                 // 8 (BN=128) or 4 (BN=64)
    constexpr int BF4 = (BK * BN / 4) / 256;    // W float4 loads per thread

    __shared__ float As[2][BK][BM + 4];
    __shared__ float Bs[2][BK][BN];

    const int z = blockIdx.z;
    const float* __restrict__ W    = (z == 0) ? W0 : (z == 1) ? W1 : (z == 2) ? W2 : W3;
    const float* __restrict__ bias = (z == 0) ? b0 : (z == 1) ? b1 : (z == 2) ? b2 : b3;
    float* __restrict__ C          = (z == 0) ? C0 : (z == 1) ? C1 : (z == 2) ? C2 : C3;

    const int tid = threadIdx.x;
    const int tx  = tid & 15;              // column group
    const int ty  = tid >> 4;              // row group
    const int rowBase = blockIdx.y * BM;
    const int colBase = blockIdx.x * BN;

    float acc[TM][TN];
#pragma unroll
    for (int i = 0; i < TM; i++)
#pragma unroll
        for (int j = 0; j < TN; j++) acc[i][j] = 0.f;

    // load mappings
    // A: idx = tid + it*256 ; row = idx>>2 ; k4 = (idx&3)*4   (2 float4/thread)
    // W: idx = tid + it*256 ; k = idx/(BN/4) ; c4 = (idx%(BN/4))*4
    float4 pa[2];
    float4 pb[BF4];

    // ---- prologue: fetch tile 0 ----
#pragma unroll
    for (int it = 0; it < 2; it++) {
        int idx = tid + it * 256;
        int r = idx >> 2, k4 = (idx & 3) << 2;
        int grow = rowBase + r;
        pa[it] = make_float4(0.f, 0.f, 0.f, 0.f);
        if (grow < M) pa[it] = *(const float4*)&A[(size_t)grow * K + k4];
    }
#pragma unroll
    for (int it = 0; it < BF4; it++) {
        int idx = tid + it * 256;
        int k = idx / (BN / 4), c4 = (idx % (BN / 4)) << 2;
        pb[it] = *(const float4*)&W[(size_t)k * Nc + colBase + c4];
    }
#pragma unroll
    for (int it = 0; it < 2; it++) {
        int idx = tid + it * 256;
        int r = idx >> 2, k4 = (idx & 3) << 2;
        As[0][k4 + 0][r] = pa[it].x;
        As[0][k4 + 1][r] = pa[it].y;
        As[0][k4 + 2][r] = pa[it].z;
        As[0][k4 + 3][r] = pa[it].w;
    }
#pragma unroll
    for (int it = 0; it < BF4; it++) {
        int idx = tid + it * 256;
        int k = idx / (BN / 4), c4 = (idx % (BN / 4)) << 2;
        *(float4*)&Bs[0][k][c4] = pb[it];
    }
    __syncthreads();

    const int nk = K / BK;
    int cur = 0;

    for (int t = 0; t < nk; t++) {
        const bool has_next = (t + 1 < nk);
        if (has_next) {
            const int kk = (t + 1) * BK;
#pragma unroll
            for (int it = 0; it < 2; it++) {
                int idx = tid + it * 256;
                int r = idx >> 2, k4 = (idx & 3) << 2;
                int grow = rowBase + r;
                pa[it] = make_float4(0.f, 0.f, 0.f, 0.f);
                if (grow < M) pa[it] = *(const float4*)&A[(size_t)grow * K + kk + k4];
            }
#pragma unroll
            for (int it = 0; it < BF4; it++) {
                int idx = tid + it * 256;
                int k = idx / (BN / 4), c4 = (idx % (BN / 4)) << 2;
                pb[it] = *(const float4*)&W[(size_t)(kk + k) * Nc + colBase + c4];
            }
        }

#pragma unroll
        for (int k = 0; k < BK; k++) {
            float a[TM];
            {
                float4 a0 = *(const float4*)&As[cur][k][ty * TM];
                float4 a1 = *(const float4*)&As[cur][k][ty * TM + 4];
                a[0] = a0.x; a[1] = a0.y; a[2] = a0.z; a[3] = a0.w;
                a[4] = a1.x; a[5] = a1.y; a[6] = a1.z; a[7] = a1.w;
            }
            float breg[TN];
#pragma unroll
            for (int j4 = 0; j4 < TN; j4 += 4) {
                float4 bv = *(const float4*)&Bs[cur][k][tx * TN + j4];
                breg[j4 + 0] = bv.x; breg[j4 + 1] = bv.y;
                breg[j4 + 2] = bv.z; breg[j4 + 3] = bv.w;
            }
#pragma unroll
            for (int i = 0; i < TM; i++)
#pragma unroll
                for (int j = 0; j < TN; j++)
                    acc[i][j] = fmaf(a[i], breg[j], acc[i][j]);
        }

        if (has_next) {
            const int nxt = cur ^ 1;
#pragma unroll
            for (int it = 0; it < 2; it++) {
                int idx = tid + it * 256;
                int r = idx >> 2, k4 = (idx & 3) << 2;
                As[nxt][k4 + 0][r] = pa[it].x;
                As[nxt][k4 + 1][r] = pa[it].y;
                As[nxt][k4 + 2][r] = pa[it].z;
                As[nxt][k4 + 3][r] = pa[it].w;
            }
#pragma unroll
            for (int it = 0; it < BF4; it++) {
                int idx = tid + it * 256;
                int k = idx / (BN / 4), c4 = (idx % (BN / 4)) << 2;
                *(float4*)&Bs[nxt][k][c4] = pb[it];
            }
            __syncthreads();
            cur = nxt;
        }
    }

    // ---- epilogue: bias + store ----
    float bv[TN];
#pragma unroll
    for (int j4 = 0; j4 < TN; j4 += 4) {
        float4 b4 = *(const float4*)&bias[colBase + tx * TN + j4];
        bv[j4 + 0] = b4.x; bv[j4 + 1] = b4.y; bv[j4 + 2] = b4.z; bv[j4 + 3] = b4.w;
    }
#pragma unroll
    for (int i = 0; i < TM; i++) {
        int grow = rowBase + ty * TM + i;
        if (grow < M) {
#pragma unroll
            for (int j4 = 0; j4 < TN; j4 += 4) {
                float4 o;
                o.x = acc[i][j4 + 0] + bv[j4 + 0];
                o.y = acc[i][j4 + 1] + bv[j4 + 1];
                o.z = acc[i][j4 + 2] + bv[j4 + 2];
                o.w = acc[i][j4 + 3] + bv[j4 + 3];
                *(float4*)&C[(size_t)grow * Nc + colBase + tx * TN + j4] = o;
            }
        }
    }
}

// ----------------------------------------------------------------------------
// Edge kernel: per (edge, 4-feature chunk):
//   m = sigmoid(K[dst] + Q[src]) * V[src];  H[dst] += m  (vector red, no return)
// ----------------------------------------------------------------------------
__global__ void edge_gate(const void* __restrict__ ei_raw,
                          const float* __restrict__ Kb,
                          const float* __restrict__ Qb,
                          const float* __restrict__ Vb,
                          float* __restrict__ H,
                          int E, int D, int cshift)
{
    long long idx = (long long)blockIdx.x * blockDim.x + threadIdx.x;
    long long total = (long long)E << cshift;
    if (idx >= total) return;
    int e = (int)(idx >> cshift);
    int c = ((int)idx & ((1 << cshift) - 1)) << 2;

    int src, dst;
    if (g_is64) {
        const long long* ei = (const long long*)ei_raw;
        src = (int)ei[e];
        dst = (int)ei[E + e];
    } else {
        const int* ei = (const int*)ei_raw;
        src = ei[e];
        dst = ei[E + e];
    }

    const float4 k = *(const float4*)&Kb[(size_t)dst * D + c];
    const float4 q = *(const float4*)&Qb[(size_t)src * D + c];
    const float4 v = *(const float4*)&Vb[(size_t)src * D + c];

    float4 m;
    m.x = v.x / (1.f + __expf(-(k.x + q.x)));
    m.y = v.y / (1.f + __expf(-(k.y + q.y)));
    m.z = v.z / (1.f + __expf(-(k.z + q.z)));
    m.w = v.w / (1.f + __expf(-(k.w + q.w)));

    float* addr = &H[(size_t)dst * D + c];
    asm volatile("red.global.add.v4.f32 [%0], {%1,%2,%3,%4};"
                 :: "l"(addr), "f"(m.x), "f"(m.y), "f"(m.z), "f"(m.w)
                 : "memory");
}

// ----------------------------------------------------------------------------
// Row softmax over 64 columns: one warp per row, 2 elems per lane.
// ----------------------------------------------------------------------------
__global__ void softmax64(const float* __restrict__ H, float* __restrict__ out, int M)
{
    int warp = threadIdx.x >> 5;
    int lane = threadIdx.x & 31;
    int row  = blockIdx.x * (blockDim.x >> 5) + warp;
    if (row >= M) return;
    float a = H[row * 64 + lane];
    float b = H[row * 64 + 32 + lane];
    float mx = fmaxf(a, b);
#pragma unroll
    for (int o = 16; o > 0; o >>= 1) mx = fmaxf(mx, __shfl_xor_sync(0xffffffffu, mx, o));
    float ea = __expf(a - mx);
    float eb = __expf(b - mx);
    float s  = ea + eb;
#pragma unroll
    for (int o = 16; o > 0; o >>= 1) s += __shfl_xor_sync(0xffffffffu, s, o);
    float inv = 1.f / s;
    out[row * 64 + lane]      = ea * inv;
    out[row * 64 + 32 + lane] = eb * inv;
}

// ----------------------------------------------------------------------------
extern "C" void kernel_launch(void* const* d_in, const int* in_sizes, int n_in,
                              void* d_out, int out_size)
{
    const float* x  = (const float*)d_in[0];
    const void*  ei = d_in[1];
    const int Nn = in_sizes[0] / 256;
    const int E  = in_sizes[1] / 2;

    float *pK, *pQ, *pV, *pHa, *pHb;
    cudaGetSymbolAddress((void**)&pK,  g_K);
    cudaGetSymbolAddress((void**)&pQ,  g_Q);
    cudaGetSymbolAddress((void**)&pV,  g_V);
    cudaGetSymbolAddress((void**)&pHa, g_Ha);
    cudaGetSymbolAddress((void**)&pHb, g_Hb);

    const float* w[26];
    for (int i = 2; i < 26; i++) w[i] = (const float*)d_in[i];

    dim3 blk(256);
    const int gy = (Nn + 127) / 128;

    detect_i64<<<1, 256>>>((const unsigned int*)ei);

    // ---- layer 1: din=256, dout=256, input x, outputs K,Q,V,Ha(skip) ----
    {
        dim3 grid(256 / 128, gy, 4);
        gemm4<128><<<grid, blk>>>(x,
            w[2], w[4], w[6], w[20],
            w[3], w[5], w[7], w[21],
            pK, pQ, pV, pHa, Nn, 256, 256);
        long long tot = (long long)E * 64;
        edge_gate<<<(unsigned)((tot + 255) / 256), blk>>>(ei, pK, pQ, pV, pHa, E, 256, 6);
    }
    // ---- layer 2: din=256, dout=128, input Ha, outputs K,Q,V,Hb ----
    {
        dim3 grid(1, gy, 4);
        gemm4<128><<<grid, blk>>>(pHa,
            w[8], w[10], w[12], w[22],
            w[9], w[11], w[13], w[23],
            pK, pQ, pV, pHb, Nn, 256, 128);
        long long tot = (long long)E * 32;
        edge_gate<<<(unsigned)((tot + 255) / 256), blk>>>(ei, pK, pQ, pV, pHb, E, 128, 5);
    }
    // ---- layer 3: din=128, dout=64, input Hb, outputs K,Q,V,Ha ----
    {
        dim3 grid(1, gy, 4);
        gemm4<64><<<grid, blk>>>(pHb,
            w[14], w[16], w[18], w[24],
            w[15], w[17], w[19], w[25],
            pK, pQ, pV, pHa, Nn, 128, 64);
        long long tot = (long long)E * 16;
        edge_gate<<<(unsigned)((tot + 255) / 256), blk>>>(ei, pK, pQ, pV, pHa, E, 64, 4);
        softmax64<<<(Nn + 7) / 8, 256>>>(pHa, (float*)d_out, Nn);
    }
}

// round 8
// speedup vs baseline: 1.6096x; 1.3957x over previous
#include <cuda_runtime.h>
#include <cuda_bf16.h>
#include <cstdint>

// ============================================================================
// ResGatedGraphConv x3 + softmax. GEMMs on mma.sync bf16 (split-precision).
//   per layer: cat = A @ [Wk|Wq|Wv|Ws]^T + [bk|bq|bv|bias]  (one fused GEMM)
//              eta = sigmoid(K[dst]+Q[src]); cat.H[dst] += eta*V[src]
//   A(fp32) -> bf16 hi+lo; C = Ahi*Whi + Ahi*Wlo + Alo*Whi (fp32 accum).
// NOTE: harness compiles via compute_103 (non-'a') -> tcgen05.ld etc. are
// unavailable; mma.sync.m16n8k16 is plain sm_80+ PTX and always compiles.
// ============================================================================

#define NMAX 20000

__device__ float         g_cat [NMAX * 1024];   // per-layer [N, 4D] output
__device__ __nv_bfloat16 g_Ahi [NMAX * 256];
__device__ __nv_bfloat16 g_Alo [NMAX * 256];
__device__ __nv_bfloat16 g_Whi [1024 * 256];    // [Ncat, K] K-major
__device__ __nv_bfloat16 g_Wlo [1024 * 256];
__device__ float         g_bias[1024];
__device__ int           g_is64;

__device__ __forceinline__ uint32_t smem_u32(const void* p) {
    uint32_t a;
    asm("{ .reg .u64 t; cvta.to.shared.u64 t, %1; cvt.u32.u64 %0, t; }" : "=r"(a) : "l"(p));
    return a;
}

__device__ __forceinline__ void ldsm_x4(uint32_t* r, uint32_t addr) {
    asm volatile("ldmatrix.sync.aligned.m8n8.x4.shared.b16 {%0,%1,%2,%3}, [%4];"
                 : "=r"(r[0]), "=r"(r[1]), "=r"(r[2]), "=r"(r[3]) : "r"(addr));
}

__device__ __forceinline__ void mma16816(float* c, const uint32_t* a,
                                         uint32_t b0, uint32_t b1) {
    asm volatile(
        "mma.sync.aligned.m16n8k16.row.col.f32.bf16.bf16.f32 "
        "{%0,%1,%2,%3}, {%4,%5,%6,%7}, {%8,%9}, {%0,%1,%2,%3};"
        : "+f"(c[0]), "+f"(c[1]), "+f"(c[2]), "+f"(c[3])
        : "r"(a[0]), "r"(a[1]), "r"(a[2]), "r"(a[3]), "r"(b0), "r"(b1));
}

// ----------------------------------------------------------------------------
// edge_index dtype detection (int64 high words all-zero for node ids < 2^31)
// ----------------------------------------------------------------------------
__global__ void detect_i64(const unsigned int* __restrict__ p) {
    __shared__ unsigned int s;
    if (threadIdx.x == 0) s = 0u;
    __syncthreads();
    unsigned int v = 0u;
    for (int i = threadIdx.x; i < 2048; i += blockDim.x) v |= p[2 * i + 1];
    atomicOr(&s, v);
    __syncthreads();
    if (threadIdx.x == 0) g_is64 = (s == 0u) ? 1 : 0;
}

// ----------------------------------------------------------------------------
// Activation convert: fp32 (strided source) -> bf16 hi/lo, [M, K] row-major
// ----------------------------------------------------------------------------
__global__ void conv_a(const float* __restrict__ src, int srcStride, int srcOff,
                       __nv_bfloat16* __restrict__ hi, __nv_bfloat16* __restrict__ lo,
                       int M, int K)
{
    int idx = blockIdx.x * blockDim.x + threadIdx.x;
    if (idx >= M * K) return;
    int n = idx / K, k = idx - n * K;
    float a = src[(size_t)n * srcStride + srcOff + k];
    __nv_bfloat16 h = __float2bfloat16(a);
    hi[idx] = h;
    lo[idx] = __float2bfloat16(a - __bfloat162float(h));
}

// ----------------------------------------------------------------------------
// Weight convert: 4x W [K, D] fp32 -> transposed concat [Ncat=4D, K] bf16 hi/lo
// plus bias_cat.
// ----------------------------------------------------------------------------
__global__ void conv_w(const float* __restrict__ W0, const float* __restrict__ W1,
                       const float* __restrict__ W2, const float* __restrict__ W3,
                       const float* __restrict__ b0, const float* __restrict__ b1,
                       const float* __restrict__ b2, const float* __restrict__ b3,
                       __nv_bfloat16* __restrict__ hi, __nv_bfloat16* __restrict__ lo,
                       float* __restrict__ biascat, int K, int D)
{
    int idx = blockIdx.x * blockDim.x + threadIdx.x;
    int Ncat = 4 * D;
    if (idx >= Ncat * K) return;
    int n = idx / K, k = idx - n * K;
    int z = n / D, jz = n - z * D;
    const float* W = (z == 0) ? W0 : (z == 1) ? W1 : (z == 2) ? W2 : W3;
    float w = W[(size_t)k * D + jz];
    __nv_bfloat16 h = __float2bfloat16(w);
    hi[idx] = h;
    lo[idx] = __float2bfloat16(w - __bfloat162float(h));
    if (k == 0) {
        const float* b = (z == 0) ? b0 : (z == 1) ? b1 : (z == 2) ? b2 : b3;
        biascat[n] = b[jz];
    }
}

// ----------------------------------------------------------------------------
// mma.sync GEMM: C[M, Ncat] = Ahi@Whi^T + Ahi@Wlo^T + Alo@Whi^T + bias
//   A*: [M, K] bf16 row-major. W*: [Ncat, K] bf16 K-major (== B col-major).
//   256 threads, CTA tile 128x128, warp tile 32x64, BK=32, double-buffered.
// ----------------------------------------------------------------------------
__global__ __launch_bounds__(256, 2)
void gemm_mma(const __nv_bfloat16* __restrict__ Ahi, const __nv_bfloat16* __restrict__ Alo,
              const __nv_bfloat16* __restrict__ Whi, const __nv_bfloat16* __restrict__ Wlo,
              const float* __restrict__ biascat, float* __restrict__ C,
              int M, int K, int Ncat)
{
    // rows padded to 40 bf16 (80 B) -> conflict-free ldmatrix, 16B-aligned segs
    __shared__ __align__(1024) __nv_bfloat16 sA[2][128][40];
    __shared__ __align__(1024) __nv_bfloat16 sW[2][128][40];

    const int tid  = threadIdx.x;
    const int wid  = tid >> 5;
    const int lane = tid & 31;
    const int wr   = wid & 3;          // warp m index (4)
    const int wc   = wid >> 2;         // warp n index (2)
    const int rowBase = blockIdx.x * 128;
    const int colBase = blockIdx.y * 128;

    const uint32_t sAu = smem_u32(sA);
    const uint32_t sWu = smem_u32(sW);
    const uint32_t BUFS = 128 * 80;    // bytes per buffer

    // ldmatrix per-thread address components (byte offsets within a buffer)
    const uint32_t aRowOff = (uint32_t)(wr * 32 + (lane & 15)) * 80;
    const uint32_t aKhalf  = (uint32_t)(lane >> 4) * 16;
    const int grp = lane >> 3;
    const uint32_t bRowOff = (uint32_t)(wc * 64 + (grp >> 1) * 8 + (lane & 7)) * 80;
    const uint32_t bKhalf  = (uint32_t)(grp & 1) * 16;

    float acc[2][8][4];
#pragma unroll
    for (int mi = 0; mi < 2; mi++)
#pragma unroll
        for (int nj = 0; nj < 8; nj++)
#pragma unroll
            for (int q = 0; q < 4; q++) acc[mi][nj][q] = 0.f;

    // global->smem mapping: 128 rows x 32 bf16 = 4 x 16B segs/row
    const int lr   = tid >> 2;     // rows lr, lr+64
    const int lseg = tid & 3;

    const int chunks = 3 * (K >> 5);
    uint4 pa[2], pw[2];

    // ---- prefetch chunk 0 ----
    {
        const __nv_bfloat16* As = Ahi;   // p=0
        const __nv_bfloat16* Ws = Whi;
        const int kOff = lseg * 8;
#pragma unroll
        for (int it = 0; it < 2; it++) {
            int r = lr + it * 64;
            int grow = rowBase + r;
            pa[it] = make_uint4(0u, 0u, 0u, 0u);
            if (grow < M) pa[it] = *(const uint4*)&As[(size_t)grow * K + kOff];
            pw[it] = *(const uint4*)&Ws[(size_t)(colBase + r) * K + kOff];
        }
    }
    {
#pragma unroll
        for (int it = 0; it < 2; it++) {
            int r = lr + it * 64;
            *(uint4*)&sA[0][r][lseg * 8] = pa[it];
            *(uint4*)&sW[0][r][lseg * 8] = pw[it];
        }
    }
    __syncthreads();

    int buf = 0;
    for (int ch = 0; ch < chunks; ch++) {
        const bool hasNext = (ch + 1 < chunks);
        if (hasNext) {
            const int nc = ch + 1;
            const int p  = nc % 3;
            const int kc = nc / 3;
            const __nv_bfloat16* As = (p == 2) ? Alo : Ahi;
            const __nv_bfloat16* Ws = (p == 1) ? Wlo : Whi;
            const int kOff = kc * 32 + lseg * 8;
#pragma unroll
            for (int it = 0; it < 2; it++) {
                int r = lr + it * 64;
                int grow = rowBase + r;
                pa[it] = make_uint4(0u, 0u, 0u, 0u);
                if (grow < M) pa[it] = *(const uint4*)&As[(size_t)grow * K + kOff];
                pw[it] = *(const uint4*)&Ws[(size_t)(colBase + r) * K + kOff];
            }
        }

        const uint32_t aBase = sAu + buf * BUFS;
        const uint32_t bBase = sWu + buf * BUFS;
#pragma unroll
        for (int ks = 0; ks < 2; ks++) {
            const uint32_t kbyte = ks * 32;
            uint32_t a[2][4];
#pragma unroll
            for (int mi = 0; mi < 2; mi++)
                ldsm_x4(a[mi], aBase + aRowOff + mi * (16 * 80) + kbyte + aKhalf);
#pragma unroll
            for (int nj2 = 0; nj2 < 4; nj2++) {
                uint32_t b[4];
                ldsm_x4(b, bBase + bRowOff + nj2 * (16 * 80) + kbyte + bKhalf);
#pragma unroll
                for (int mi = 0; mi < 2; mi++) {
                    mma16816(acc[mi][nj2 * 2 + 0], a[mi], b[0], b[1]);
                    mma16816(acc[mi][nj2 * 2 + 1], a[mi], b[2], b[3]);
                }
            }
        }

        if (hasNext) {
            const int nxt = buf ^ 1;
            __syncthreads();
#pragma unroll
            for (int it = 0; it < 2; it++) {
                int r = lr + it * 64;
                *(uint4*)&sA[nxt][r][lseg * 8] = pa[it];
                *(uint4*)&sW[nxt][r][lseg * 8] = pw[it];
            }
            __syncthreads();
            buf = nxt;
        }
    }

    // ---- epilogue: +bias, store (fragment layout: rows lane/4, +8; cols 2(lane%4)) ----
    const int rBase0 = rowBase + wr * 32 + (lane >> 2);
    const int cBase  = colBase + wc * 64 + ((lane & 3) << 1);
#pragma unroll
    for (int mi = 0; mi < 2; mi++) {
        int r0 = rBase0 + mi * 16;
        int r1 = r0 + 8;
#pragma unroll
        for (int nj = 0; nj < 8; nj++) {
            int col = cBase + nj * 8;
            float2 b2 = *(const float2*)&biascat[col];
            if (r0 < M) {
                float2 o = make_float2(acc[mi][nj][0] + b2.x, acc[mi][nj][1] + b2.y);
                *(float2*)&C[(size_t)r0 * Ncat + col] = o;
            }
            if (r1 < M) {
                float2 o = make_float2(acc[mi][nj][2] + b2.x, acc[mi][nj][3] + b2.y);
                *(float2*)&C[(size_t)r1 * Ncat + col] = o;
            }
        }
    }
}

// ----------------------------------------------------------------------------
// Edge kernel on concatenated layout: K at +0, Q at +D, V at +2D, H at +3D.
//   m = sigmoid(K[dst]+Q[src]) * V[src];  H[dst] += m (red.global.v4)
// ----------------------------------------------------------------------------
__global__ void edge_gate(const void* __restrict__ ei_raw,
                          float* __restrict__ cat,
                          int E, int D, int stride, int cshift)
{
    long long idx = (long long)blockIdx.x * blockDim.x + threadIdx.x;
    long long total = (long long)E << cshift;
    if (idx >= total) return;
    int e = (int)(idx >> cshift);
    int c = ((int)idx & ((1 << cshift) - 1)) << 2;

    int src, dst;
    if (g_is64) {
        const long long* ei = (const long long*)ei_raw;
        src = (int)ei[e];
        dst = (int)ei[E + e];
    } else {
        const int* ei = (const int*)ei_raw;
        src = ei[e];
        dst = ei[E + e];
    }

    const float4 k = *(const float4*)&cat[(size_t)dst * stride + c];
    const float4 q = *(const float4*)&cat[(size_t)src * stride + D + c];
    const float4 v = *(const float4*)&cat[(size_t)src * stride + 2 * D + c];

    float4 m;
    m.x = v.x / (1.f + __expf(-(k.x + q.x)));
    m.y = v.y / (1.f + __expf(-(k.y + q.y)));
    m.z = v.z / (1.f + __expf(-(k.z + q.z)));
    m.w = v.w / (1.f + __expf(-(k.w + q.w)));

    float* addr = &cat[(size_t)dst * stride + 3 * D + c];
    asm volatile("red.global.add.v4.f32 [%0], {%1,%2,%3,%4};"
                 :: "l"(addr), "f"(m.x), "f"(m.y), "f"(m.z), "f"(m.w)
                 : "memory");
}

// ----------------------------------------------------------------------------
// Row softmax over 64 cols (strided source): one warp per row.
// ----------------------------------------------------------------------------
__global__ void softmax64(const float* __restrict__ H, int stride, int off,
                          float* __restrict__ out, int M)
{
    int warp = threadIdx.x >> 5;
    int lane = threadIdx.x & 31;
    int row  = blockIdx.x * (blockDim.x >> 5) + warp;
    if (row >= M) return;
    float a = H[(size_t)row * stride + off + lane];
    float b = H[(size_t)row * stride + off + 32 + lane];
    float mx = fmaxf(a, b);
#pragma unroll
    for (int o = 16; o > 0; o >>= 1) mx = fmaxf(mx, __shfl_xor_sync(0xffffffffu, mx, o));
    float ea = __expf(a - mx);
    float eb = __expf(b - mx);
    float s  = ea + eb;
#pragma unroll
    for (int o = 16; o > 0; o >>= 1) s += __shfl_xor_sync(0xffffffffu, s, o);
    float inv = 1.f / s;
    out[row * 64 + lane]      = ea * inv;
    out[row * 64 + 32 + lane] = eb * inv;
}

// ----------------------------------------------------------------------------
extern "C" void kernel_launch(void* const* d_in, const int* in_sizes, int n_in,
                              void* d_out, int out_size)
{
    const float* x  = (const float*)d_in[0];
    const void*  ei = d_in[1];
    const int Nn = in_sizes[0] / 256;
    const int E  = in_sizes[1] / 2;

    float *pCat, *pBias;
    __nv_bfloat16 *pAhi, *pAlo, *pWhi, *pWlo;
    cudaGetSymbolAddress((void**)&pCat,  g_cat);
    cudaGetSymbolAddress((void**)&pAhi,  g_Ahi);
    cudaGetSymbolAddress((void**)&pAlo,  g_Alo);
    cudaGetSymbolAddress((void**)&pWhi,  g_Whi);
    cudaGetSymbolAddress((void**)&pWlo,  g_Wlo);
    cudaGetSymbolAddress((void**)&pBias, g_bias);

    const float* w[26];
    for (int i = 2; i < 26; i++) w[i] = (const float*)d_in[i];

    const int gm = (Nn + 127) / 128;   // 157 M-tiles
    detect_i64<<<1, 256>>>((const unsigned int*)ei);

    // ---- layer 1: K=256, D=256, Ncat=1024 ----
    conv_w<<<(1024 * 256 + 255) / 256, 256>>>(
        w[2], w[4], w[6], w[20], w[3], w[5], w[7], w[21],
        pWhi, pWlo, pBias, 256, 256);
    conv_a<<<(Nn * 256 + 255) / 256, 256>>>(x, 256, 0, pAhi, pAlo, Nn, 256);
    gemm_mma<<<dim3(gm, 8), 256>>>(pAhi, pAlo, pWhi, pWlo, pBias, pCat, Nn, 256, 1024);
    {
        long long tot = (long long)E * 64;
        edge_gate<<<(unsigned)((tot + 255) / 256), 256>>>(ei, pCat, E, 256, 1024, 6);
    }

    // ---- layer 2: K=256, D=128, Ncat=512 ----
    conv_w<<<(512 * 256 + 255) / 256, 256>>>(
        w[8], w[10], w[12], w[22], w[9], w[11], w[13], w[23],
        pWhi, pWlo, pBias, 256, 128);
    conv_a<<<(Nn * 256 + 255) / 256, 256>>>(pCat, 1024, 768, pAhi, pAlo, Nn, 256);
    gemm_mma<<<dim3(gm, 4), 256>>>(pAhi, pAlo, pWhi, pWlo, pBias, pCat, Nn, 256, 512);
    {
        long long tot = (long long)E * 32;
        edge_gate<<<(unsigned)((tot + 255) / 256), 256>>>(ei, pCat, E, 128, 512, 5);
    }

    // ---- layer 3: K=128, D=64, Ncat=256 ----
    conv_w<<<(256 * 128 + 255) / 256, 256>>>(
        w[14], w[16], w[18], w[24], w[15], w[17], w[19], w[25],
        pWhi, pWlo, pBias, 128, 64);
    conv_a<<<(Nn * 128 + 255) / 256, 256>>>(pCat, 512, 384, pAhi, pAlo, Nn, 128);
    gemm_mma<<<dim3(gm, 2), 256>>>(pAhi, pAlo, pWhi, pWlo, pBias, pCat, Nn, 128, 256);
    {
        long long tot = (long long)E * 16;
        edge_gate<<<(unsigned)((tot + 255) / 256), 256>>>(ei, pCat, E, 64, 256, 4);
    }

    softmax64<<<(Nn + 7) / 8, 256>>>(pCat, 256, 192, (float*)d_out, Nn);
}

// round 9
// speedup vs baseline: 1.7077x; 1.0609x over previous
#include <cuda_runtime.h>
#include <cuda_bf16.h>
#include <cstdint>

// ============================================================================
// ResGatedGraphConv x3 + softmax. GEMMs on mma.sync bf16 (split-precision).
//   per layer: cat = A @ [Wk|Wq|Wv|Ws]^T + [bk|bq|bv|bias]  (one fused GEMM)
//              eta = sigmoid(K[dst]+Q[src]); cat.H[dst] += eta*V[src]
//   A(fp32) -> bf16 hi+lo; C = Ahi*Whi + Ahi*Wlo + Alo*Whi (fp32 accum).
// GEMM: 128 thr / 4 warps, CTA 128x128, warp tile 64x64, cp.async double buffer.
// ============================================================================

#define NMAX 20000

__device__ float         g_cat [NMAX * 1024];   // per-layer [N, 4D] output
__device__ __nv_bfloat16 g_Ahi [NMAX * 256];
__device__ __nv_bfloat16 g_Alo [NMAX * 256];
__device__ __nv_bfloat16 g_Whi [1024 * 256];    // [Ncat, K] K-major
__device__ __nv_bfloat16 g_Wlo [1024 * 256];
__device__ float         g_bias[1024];
__device__ int           g_is64;

__device__ __forceinline__ uint32_t smem_u32(const void* p) {
    uint32_t a;
    asm("{ .reg .u64 t; cvta.to.shared.u64 t, %1; cvt.u32.u64 %0, t; }" : "=r"(a) : "l"(p));
    return a;
}

__device__ __forceinline__ void ldsm_x4(uint32_t* r, uint32_t addr) {
    asm volatile("ldmatrix.sync.aligned.m8n8.x4.shared.b16 {%0,%1,%2,%3}, [%4];"
                 : "=r"(r[0]), "=r"(r[1]), "=r"(r[2]), "=r"(r[3]) : "r"(addr));
}

__device__ __forceinline__ void mma16816(float* c, const uint32_t* a,
                                         uint32_t b0, uint32_t b1) {
    asm volatile(
        "mma.sync.aligned.m16n8k16.row.col.f32.bf16.bf16.f32 "
        "{%0,%1,%2,%3}, {%4,%5,%6,%7}, {%8,%9}, {%0,%1,%2,%3};"
        : "+f"(c[0]), "+f"(c[1]), "+f"(c[2]), "+f"(c[3])
        : "r"(a[0]), "r"(a[1]), "r"(a[2]), "r"(a[3]), "r"(b0), "r"(b1));
}

#define CP_ASYNC16(dst, src, sz) \
    asm volatile("cp.async.cg.shared.global [%0], [%1], 16, %2;" \
                 :: "r"(dst), "l"(src), "r"(sz))
#define CP_COMMIT()  asm volatile("cp.async.commit_group;" ::: "memory")
#define CP_WAIT0()   asm volatile("cp.async.wait_group 0;" ::: "memory")

// ----------------------------------------------------------------------------
// edge_index dtype detection (int64 high words all-zero for node ids < 2^31)
// ----------------------------------------------------------------------------
__global__ void detect_i64(const unsigned int* __restrict__ p) {
    __shared__ unsigned int s;
    if (threadIdx.x == 0) s = 0u;
    __syncthreads();
    unsigned int v = 0u;
    for (int i = threadIdx.x; i < 2048; i += blockDim.x) v |= p[2 * i + 1];
    atomicOr(&s, v);
    __syncthreads();
    if (threadIdx.x == 0) g_is64 = (s == 0u) ? 1 : 0;
}

// ----------------------------------------------------------------------------
// Activation convert: fp32 (strided source) -> bf16 hi/lo, [M, K] row-major
// ----------------------------------------------------------------------------
__global__ void conv_a(const float* __restrict__ src, int srcStride, int srcOff,
                       __nv_bfloat16* __restrict__ hi, __nv_bfloat16* __restrict__ lo,
                       int M, int K)
{
    int idx = blockIdx.x * blockDim.x + threadIdx.x;
    if (idx >= M * K) return;
    int n = idx / K, k = idx - n * K;
    float a = src[(size_t)n * srcStride + srcOff + k];
    __nv_bfloat16 h = __float2bfloat16(a);
    hi[idx] = h;
    lo[idx] = __float2bfloat16(a - __bfloat162float(h));
}

// ----------------------------------------------------------------------------
// Weight convert: 4x W [K, D] fp32 -> transposed concat [Ncat=4D, K] bf16 hi/lo
// plus bias_cat.
// ----------------------------------------------------------------------------
__global__ void conv_w(const float* __restrict__ W0, const float* __restrict__ W1,
                       const float* __restrict__ W2, const float* __restrict__ W3,
                       const float* __restrict__ b0, const float* __restrict__ b1,
                       const float* __restrict__ b2, const float* __restrict__ b3,
                       __nv_bfloat16* __restrict__ hi, __nv_bfloat16* __restrict__ lo,
                       float* __restrict__ biascat, int K, int D)
{
    int idx = blockIdx.x * blockDim.x + threadIdx.x;
    int Ncat = 4 * D;
    if (idx >= Ncat * K) return;
    int n = idx / K, k = idx - n * K;
    int z = n / D, jz = n - z * D;
    const float* W = (z == 0) ? W0 : (z == 1) ? W1 : (z == 2) ? W2 : W3;
    float w = W[(size_t)k * D + jz];
    __nv_bfloat16 h = __float2bfloat16(w);
    hi[idx] = h;
    lo[idx] = __float2bfloat16(w - __bfloat162float(h));
    if (k == 0) {
        const float* b = (z == 0) ? b0 : (z == 1) ? b1 : (z == 2) ? b2 : b3;
        biascat[n] = b[jz];
    }
}

// ----------------------------------------------------------------------------
// mma.sync GEMM: C[M, Ncat] = Ahi@Whi^T + Ahi@Wlo^T + Alo@Whi^T + bias
//   A*: [M, K] bf16 row-major. W*: [Ncat, K] bf16 K-major (== B col-major).
//   128 threads / 4 warps (2x2), CTA tile 128x128, warp tile 64x64, BK=32,
//   cp.async double-buffered smem (rows padded to 40 bf16 -> conflict-free).
// ----------------------------------------------------------------------------
__global__ __launch_bounds__(128)
void gemm_mma(const __nv_bfloat16* __restrict__ Ahi, const __nv_bfloat16* __restrict__ Alo,
              const __nv_bfloat16* __restrict__ Whi, const __nv_bfloat16* __restrict__ Wlo,
              const float* __restrict__ biascat, float* __restrict__ C,
              int M, int K, int Ncat)
{
    __shared__ __align__(1024) __nv_bfloat16 sA[2][128][40];
    __shared__ __align__(1024) __nv_bfloat16 sW[2][128][40];

    const int tid  = threadIdx.x;
    const int wid  = tid >> 5;
    const int lane = tid & 31;
    const int wr   = wid & 1;          // warp m index (2)
    const int wc   = wid >> 1;         // warp n index (2)
    const int rowBase = blockIdx.x * 128;
    const int colBase = blockIdx.y * 128;

    const uint32_t sAu = smem_u32(sA);
    const uint32_t sWu = smem_u32(sW);
    const uint32_t BUFS = 128 * 80;    // bytes per buffer

    // ldmatrix per-thread address components (byte offsets within a buffer)
    const uint32_t aRowOff = (uint32_t)(wr * 64 + (lane & 15)) * 80;
    const uint32_t aKhalf  = (uint32_t)(lane >> 4) * 16;
    const int grp = lane >> 3;
    const uint32_t bRowOff = (uint32_t)(wc * 64 + (grp >> 1) * 8 + (lane & 7)) * 80;
    const uint32_t bKhalf  = (uint32_t)(grp & 1) * 16;

    float acc[4][8][4];
#pragma unroll
    for (int mi = 0; mi < 4; mi++)
#pragma unroll
        for (int nj = 0; nj < 8; nj++)
#pragma unroll
            for (int q = 0; q < 4; q++) acc[mi][nj][q] = 0.f;

    // cp.async mapping: tile = 128 rows x 4 x 16B segs; 128 threads -> 4 each
    const int lr   = tid >> 2;         // base row; rows lr + it*32
    const int lseg = tid & 3;

    const int chunks = 3 * (K >> 5);

    // ---- issue chunk 0 ----
    {
        const int kOff = lseg * 8;
#pragma unroll
        for (int it = 0; it < 4; it++) {
            int r = lr + it * 32;
            int grow = rowBase + r;
            uint32_t dst = (uint32_t)(r * 80 + lseg * 16);
            const __nv_bfloat16* asrc = &Ahi[(size_t)(grow < M ? grow : 0) * K + kOff];
            CP_ASYNC16(sAu + dst, asrc, (grow < M) ? 16 : 0);
            CP_ASYNC16(sWu + dst, &Whi[(size_t)(colBase + r) * K + kOff], 16);
        }
        CP_COMMIT();
    }
    CP_WAIT0();
    __syncthreads();

    int buf = 0;
    for (int ch = 0; ch < chunks; ch++) {
        const bool hasNext = (ch + 1 < chunks);
        if (hasNext) {
            const int nc = ch + 1;
            const int p  = nc % 3;
            const int kc = nc / 3;
            const __nv_bfloat16* __restrict__ As = (p == 2) ? Alo : Ahi;
            const __nv_bfloat16* __restrict__ Ws = (p == 1) ? Wlo : Whi;
            const int kOff = kc * 32 + lseg * 8;
            const uint32_t bb = (uint32_t)((buf ^ 1) * BUFS);
#pragma unroll
            for (int it = 0; it < 4; it++) {
                int r = lr + it * 32;
                int grow = rowBase + r;
                uint32_t dst = bb + (uint32_t)(r * 80 + lseg * 16);
                const __nv_bfloat16* asrc = &As[(size_t)(grow < M ? grow : 0) * K + kOff];
                CP_ASYNC16(sAu + dst, asrc, (grow < M) ? 16 : 0);
                CP_ASYNC16(sWu + dst, &Ws[(size_t)(colBase + r) * K + kOff], 16);
            }
            CP_COMMIT();
        }

        const uint32_t aBase = sAu + buf * BUFS;
        const uint32_t bBase = sWu + buf * BUFS;
#pragma unroll
        for (int ks = 0; ks < 2; ks++) {
            const uint32_t kbyte = ks * 32;
            uint32_t a[4][4];
#pragma unroll
            for (int mi = 0; mi < 4; mi++)
                ldsm_x4(a[mi], aBase + aRowOff + mi * (16 * 80) + kbyte + aKhalf);
#pragma unroll
            for (int nj2 = 0; nj2 < 4; nj2++) {
                uint32_t b[4];
                ldsm_x4(b, bBase + bRowOff + nj2 * (16 * 80) + kbyte + bKhalf);
#pragma unroll
                for (int mi = 0; mi < 4; mi++) {
                    mma16816(acc[mi][nj2 * 2 + 0], a[mi], b[0], b[1]);
                    mma16816(acc[mi][nj2 * 2 + 1], a[mi], b[2], b[3]);
                }
            }
        }

        if (hasNext) {
            CP_WAIT0();
            __syncthreads();
            buf ^= 1;
        }
    }

    // ---- epilogue: +bias, store (rows lane/4, +8; cols 2(lane%4)) ----
    const int rBase0 = rowBase + wr * 64 + (lane >> 2);
    const int cBase  = colBase + wc * 64 + ((lane & 3) << 1);
#pragma unroll
    for (int mi = 0; mi < 4; mi++) {
        int r0 = rBase0 + mi * 16;
        int r1 = r0 + 8;
#pragma unroll
        for (int nj = 0; nj < 8; nj++) {
            int col = cBase + nj * 8;
            float2 b2 = *(const float2*)&biascat[col];
            if (r0 < M) {
                float2 o = make_float2(acc[mi][nj][0] + b2.x, acc[mi][nj][1] + b2.y);
                *(float2*)&C[(size_t)r0 * Ncat + col] = o;
            }
            if (r1 < M) {
                float2 o = make_float2(acc[mi][nj][2] + b2.x, acc[mi][nj][3] + b2.y);
                *(float2*)&C[(size_t)r1 * Ncat + col] = o;
            }
        }
    }
}

// ----------------------------------------------------------------------------
// Edge kernel on concatenated layout: K at +0, Q at +D, V at +2D, H at +3D.
//   m = sigmoid(K[dst]+Q[src]) * V[src];  H[dst] += m (red.global.v4)
// ----------------------------------------------------------------------------
__global__ void edge_gate(const void* __restrict__ ei_raw,
                          float* __restrict__ cat,
                          int E, int D, int stride, int cshift)
{
    long long idx = (long long)blockIdx.x * blockDim.x + threadIdx.x;
    long long total = (long long)E << cshift;
    if (idx >= total) return;
    int e = (int)(idx >> cshift);
    int c = ((int)idx & ((1 << cshift) - 1)) << 2;

    int src, dst;
    if (g_is64) {
        const long long* ei = (const long long*)ei_raw;
        src = (int)ei[e];
        dst = (int)ei[E + e];
    } else {
        const int* ei = (const int*)ei_raw;
        src = ei[e];
        dst = ei[E + e];
    }

    const float4 k = *(const float4*)&cat[(size_t)dst * stride + c];
    const float4 q = *(const float4*)&cat[(size_t)src * stride + D + c];
    const float4 v = *(const float4*)&cat[(size_t)src * stride + 2 * D + c];

    float4 m;
    m.x = v.x / (1.f + __expf(-(k.x + q.x)));
    m.y = v.y / (1.f + __expf(-(k.y + q.y)));
    m.z = v.z / (1.f + __expf(-(k.z + q.z)));
    m.w = v.w / (1.f + __expf(-(k.w + q.w)));

    float* addr = &cat[(size_t)dst * stride + 3 * D + c];
    asm volatile("red.global.add.v4.f32 [%0], {%1,%2,%3,%4};"
                 :: "l"(addr), "f"(m.x), "f"(m.y), "f"(m.z), "f"(m.w)
                 : "memory");
}

// ----------------------------------------------------------------------------
// Row softmax over 64 cols (strided source): one warp per row.
// ----------------------------------------------------------------------------
__global__ void softmax64(const float* __restrict__ H, int stride, int off,
                          float* __restrict__ out, int M)
{
    int warp = threadIdx.x >> 5;
    int lane = threadIdx.x & 31;
    int row  = blockIdx.x * (blockDim.x >> 5) + warp;
    if (row >= M) return;
    float a = H[(size_t)row * stride + off + lane];
    float b = H[(size_t)row * stride + off + 32 + lane];
    float mx = fmaxf(a, b);
#pragma unroll
    for (int o = 16; o > 0; o >>= 1) mx = fmaxf(mx, __shfl_xor_sync(0xffffffffu, mx, o));
    float ea = __expf(a - mx);
    float eb = __expf(b - mx);
    float s  = ea + eb;
#pragma unroll
    for (int o = 16; o > 0; o >>= 1) s += __shfl_xor_sync(0xffffffffu, s, o);
    float inv = 1.f / s;
    out[row * 64 + lane]      = ea * inv;
    out[row * 64 + 32 + lane] = eb * inv;
}

// ----------------------------------------------------------------------------
extern "C" void kernel_launch(void* const* d_in, const int* in_sizes, int n_in,
                              void* d_out, int out_size)
{
    const float* x  = (const float*)d_in[0];
    const void*  ei = d_in[1];
    const int Nn = in_sizes[0] / 256;
    const int E  = in_sizes[1] / 2;

    float *pCat, *pBias;
    __nv_bfloat16 *pAhi, *pAlo, *pWhi, *pWlo;
    cudaGetSymbolAddress((void**)&pCat,  g_cat);
    cudaGetSymbolAddress((void**)&pAhi,  g_Ahi);
    cudaGetSymbolAddress((void**)&pAlo,  g_Alo);
    cudaGetSymbolAddress((void**)&pWhi,  g_Whi);
    cudaGetSymbolAddress((void**)&pWlo,  g_Wlo);
    cudaGetSymbolAddress((void**)&pBias, g_bias);

    const float* w[26];
    for (int i = 2; i < 26; i++) w[i] = (const float*)d_in[i];

    const int gm = (Nn + 127) / 128;   // 157 M-tiles
    detect_i64<<<1, 256>>>((const unsigned int*)ei);

    // ---- layer 1: K=256, D=256, Ncat=1024 ----
    conv_w<<<(1024 * 256 + 255) / 256, 256>>>(
        w[2], w[4], w[6], w[20], w[3], w[5], w[7], w[21],
        pWhi, pWlo, pBias, 256, 256);
    conv_a<<<(Nn * 256 + 255) / 256, 256>>>(x, 256, 0, pAhi, pAlo, Nn, 256);
    gemm_mma<<<dim3(gm, 8), 128>>>(pAhi, pAlo, pWhi, pWlo, pBias, pCat, Nn, 256, 1024);
    {
        long long tot = (long long)E * 64;
        edge_gate<<<(unsigned)((tot + 255) / 256), 256>>>(ei, pCat, E, 256, 1024, 6);
    }

    // ---- layer 2: K=256, D=128, Ncat=512 ----
    conv_w<<<(512 * 256 + 255) / 256, 256>>>(
        w[8], w[10], w[12], w[22], w[9], w[11], w[13], w[23],
        pWhi, pWlo, pBias, 256, 128);
    conv_a<<<(Nn * 256 + 255) / 256, 256>>>(pCat, 1024, 768, pAhi, pAlo, Nn, 256);
    gemm_mma<<<dim3(gm, 4), 128>>>(pAhi, pAlo, pWhi, pWlo, pBias, pCat, Nn, 256, 512);
    {
        long long tot = (long long)E * 32;
        edge_gate<<<(unsigned)((tot + 255) / 256), 256>>>(ei, pCat, E, 128, 512, 5);
    }

    // ---- layer 3: K=128, D=64, Ncat=256 ----
    conv_w<<<(256 * 128 + 255) / 256, 256>>>(
        w[14], w[16], w[18], w[24], w[15], w[17], w[19], w[25],
        pWhi, pWlo, pBias, 128, 64);
    conv_a<<<(Nn * 128 + 255) / 256, 256>>>(pCat, 512, 384, pAhi, pAlo, Nn, 128);
    gemm_mma<<<dim3(gm, 2), 128>>>(pAhi, pAlo, pWhi, pWlo, pBias, pCat, Nn, 128, 256);
    {
        long long tot = (long long)E * 16;
        edge_gate<<<(unsigned)((tot + 255) / 256), 256>>>(ei, pCat, E, 64, 256, 4);
    }

    softmax64<<<(Nn + 7) / 8, 256>>>(pCat, 256, 192, (float*)d_out, Nn);
}

// round 11
// speedup vs baseline: 1.8860x; 1.1044x over previous
#include <cuda_runtime.h>
#include <cuda_bf16.h>
#include <cstdint>

// ============================================================================
// ResGatedGraphConv x3 + softmax. GEMMs on mma.sync bf16 (split-precision).
//   per layer: cat = A @ [Wk|Wq|Wv|Ws]^T + [bk|bq|bv|bias]  (one fused GEMM)
//              eta = sigmoid(K[dst]+Q[src]); cat.H[dst] += eta*V[src]
//   A(fp32) -> bf16 hi+lo; C = Ahi*Whi + Ahi*Wlo + Alo*Whi (fp32 accum).
// GEMM: 128 thr / 4 warps, CTA 128x128, warp 64x64, BK=64, XOR-swizzled smem,
// cp.async double buffer (dynamic smem, 64 KB).
// ============================================================================

#define NMAX 20000

__device__ float         g_cat [NMAX * 1024];   // per-layer [N, 4D] output
__device__ __nv_bfloat16 g_Ahi [NMAX * 256];
__device__ __nv_bfloat16 g_Alo [NMAX * 256];
__device__ __nv_bfloat16 g_Whi [1024 * 256];    // [Ncat, K] K-major
__device__ __nv_bfloat16 g_Wlo [1024 * 256];
__device__ float         g_bias[1024];
__device__ int           g_is64;

__device__ __forceinline__ uint32_t smem_u32(const void* p) {
    uint32_t a;
    asm("{ .reg .u64 t; cvta.to.shared.u64 t, %1; cvt.u32.u64 %0, t; }" : "=r"(a) : "l"(p));
    return a;
}

__device__ __forceinline__ void ldsm_x4(uint32_t* r, uint32_t addr) {
    asm volatile("ldmatrix.sync.aligned.m8n8.x4.shared.b16 {%0,%1,%2,%3}, [%4];"
                 : "=r"(r[0]), "=r"(r[1]), "=r"(r[2]), "=r"(r[3]) : "r"(addr));
}

__device__ __forceinline__ void mma16816(float* c, const uint32_t* a,
                                         uint32_t b0, uint32_t b1) {
    asm volatile(
        "mma.sync.aligned.m16n8k16.row.col.f32.bf16.bf16.f32 "
        "{%0,%1,%2,%3}, {%4,%5,%6,%7}, {%8,%9}, {%0,%1,%2,%3};"
        : "+f"(c[0]), "+f"(c[1]), "+f"(c[2]), "+f"(c[3])
        : "r"(a[0]), "r"(a[1]), "r"(a[2]), "r"(a[3]), "r"(b0), "r"(b1));
}

#define CP_ASYNC16(dst, src, sz) \
    asm volatile("cp.async.cg.shared.global [%0], [%1], 16, %2;" \
                 :: "r"(dst), "l"(src), "r"(sz))
#define CP_COMMIT()  asm volatile("cp.async.commit_group;" ::: "memory")
#define CP_WAIT0()   asm volatile("cp.async.wait_group 0;" ::: "memory")

// ----------------------------------------------------------------------------
// edge_index dtype detection (int64 high words all-zero for node ids < 2^31)
// ----------------------------------------------------------------------------
__global__ void detect_i64(const unsigned int* __restrict__ p) {
    __shared__ unsigned int s;
    if (threadIdx.x == 0) s = 0u;
    __syncthreads();
    unsigned int v = 0u;
    for (int i = threadIdx.x; i < 2048; i += blockDim.x) v |= p[2 * i + 1];
    atomicOr(&s, v);
    __syncthreads();
    if (threadIdx.x == 0) g_is64 = (s == 0u) ? 1 : 0;
}

// ----------------------------------------------------------------------------
// Activation convert: fp32 (strided source) -> bf16 hi/lo, [M, K] row-major
// ----------------------------------------------------------------------------
__global__ void conv_a(const float* __restrict__ src, int srcStride, int srcOff,
                       __nv_bfloat16* __restrict__ hi, __nv_bfloat16* __restrict__ lo,
                       int M, int K)
{
    int idx = blockIdx.x * blockDim.x + threadIdx.x;
    if (idx >= M * K) return;
    int n = idx / K, k = idx - n * K;
    float a = src[(size_t)n * srcStride + srcOff + k];
    __nv_bfloat16 h = __float2bfloat16(a);
    hi[idx] = h;
    lo[idx] = __float2bfloat16(a - __bfloat162float(h));
}

// ----------------------------------------------------------------------------
// Weight convert: 4x W [K, D] fp32 -> transposed concat [Ncat=4D, K] bf16 hi/lo
// plus bias_cat.
// ----------------------------------------------------------------------------
__global__ void conv_w(const float* __restrict__ W0, const float* __restrict__ W1,
                       const float* __restrict__ W2, const float* __restrict__ W3,
                       const float* __restrict__ b0, const float* __restrict__ b1,
                       const float* __restrict__ b2, const float* __restrict__ b3,
                       __nv_bfloat16* __restrict__ hi, __nv_bfloat16* __restrict__ lo,
                       float* __restrict__ biascat, int K, int D)
{
    int idx = blockIdx.x * blockDim.x + threadIdx.x;
    int Ncat = 4 * D;
    if (idx >= Ncat * K) return;
    int n = idx / K, k = idx - n * K;
    int z = n / D, jz = n - z * D;
    const float* W = (z == 0) ? W0 : (z == 1) ? W1 : (z == 2) ? W2 : W3;
    float w = W[(size_t)k * D + jz];
    __nv_bfloat16 h = __float2bfloat16(w);
    hi[idx] = h;
    lo[idx] = __float2bfloat16(w - __bfloat162float(h));
    if (k == 0) {
        const float* b = (z == 0) ? b0 : (z == 1) ? b1 : (z == 2) ? b2 : b3;
        biascat[n] = b[jz];
    }
}

// ----------------------------------------------------------------------------
// mma.sync GEMM: C[M, Ncat] = Ahi@Whi^T + Ahi@Wlo^T + Alo@Whi^T + bias
//   A*: [M, K] bf16 row-major. W*: [Ncat, K] bf16 K-major (== B col-major).
//   128 threads / 4 warps (2x2), CTA tile 128x128, warp 64x64, BK=64.
//   Smem: 2 stages x (A,W) x 128 rows x 128 B, XOR swizzle seg^=(row&7).
// ----------------------------------------------------------------------------
#define STAGE_BYTES 16384          // 128 rows * 128 B
#define ABUF_BYTES  (2 * STAGE_BYTES)

__global__ __launch_bounds__(128)
void gemm_mma(const __nv_bfloat16* __restrict__ Ahi, const __nv_bfloat16* __restrict__ Alo,
              const __nv_bfloat16* __restrict__ Whi, const __nv_bfloat16* __restrict__ Wlo,
              const float* __restrict__ biascat, float* __restrict__ C,
              int M, int K, int Ncat)
{
    extern __shared__ __align__(1024) char dynsmem[];

    const int tid  = threadIdx.x;
    const int wid  = tid >> 5;
    const int lane = tid & 31;
    const int wr   = wid & 1;          // warp m index (2)
    const int wc   = wid >> 1;         // warp n index (2)
    const int rowBase = blockIdx.x * 128;
    const int colBase = blockIdx.y * 128;

    const uint32_t sBase = smem_u32(dynsmem);     // A stages at +0, W at +32KB

    // ldmatrix per-thread row/seg components
    const int aRowL = (lane & 15);
    const int aSegH = (lane >> 4);          // +0/+1 seg within k-step
    const int grp   = lane >> 3;
    const int bRowL = (grp >> 1) * 8 + (lane & 7);
    const int bSegH = (grp & 1);

    float acc[4][8][4];
#pragma unroll
    for (int mi = 0; mi < 4; mi++)
#pragma unroll
        for (int nj = 0; nj < 8; nj++)
#pragma unroll
            for (int q = 0; q < 4; q++) acc[mi][nj][q] = 0.f;

    const int chunks = 3 * (K >> 6);

    // cp.async loader: 8 iters x 128 thr cover 128 rows x 8 segs (16B each)
    auto issue = [&](int stage, int p, int kc) {
        const __nv_bfloat16* __restrict__ As = (p == 2) ? Alo : Ahi;
        const __nv_bfloat16* __restrict__ Ws = (p == 1) ? Wlo : Whi;
        const int kOff = kc << 6;
        const uint32_t aSt = sBase + stage * STAGE_BYTES;
        const uint32_t wSt = sBase + ABUF_BYTES + stage * STAGE_BYTES;
#pragma unroll
        for (int it = 0; it < 8; it++) {
            int idx  = it * 128 + tid;
            int r    = idx >> 3;
            int kseg = idx & 7;
            uint32_t doff = (uint32_t)(r * 128 + ((kseg ^ (r & 7)) << 4));
            int grow = rowBase + r;
            const __nv_bfloat16* asrc = &As[(size_t)(grow < M ? grow : 0) * K + kOff + kseg * 8];
            CP_ASYNC16(aSt + doff, asrc, (grow < M) ? 16 : 0);
            CP_ASYNC16(wSt + doff, &Ws[(size_t)(colBase + r) * K + kOff + kseg * 8], 16);
        }
        CP_COMMIT();
    };

    issue(0, 0, 0);
    CP_WAIT0();
    __syncthreads();

    int buf = 0;
    for (int ch = 0; ch < chunks; ch++) {
        const bool hasNext = (ch + 1 < chunks);
        if (hasNext) {
            const int nc = ch + 1;
            issue(buf ^ 1, nc % 3, nc / 3);
        }

        const uint32_t aBase = sBase + buf * STAGE_BYTES;
        const uint32_t bBase = sBase + ABUF_BYTES + buf * STAGE_BYTES;
#pragma unroll
        for (int ks = 0; ks < 4; ks++) {
            uint32_t a[4][4];
#pragma unroll
            for (int mi = 0; mi < 4; mi++) {
                int r = wr * 64 + mi * 16 + aRowL;
                uint32_t seg = (uint32_t)((ks * 2 + aSegH) ^ (r & 7));
                ldsm_x4(a[mi], aBase + (uint32_t)(r * 128) + (seg << 4));
            }
#pragma unroll
            for (int nj2 = 0; nj2 < 4; nj2++) {
                uint32_t b[4];
                int r = wc * 64 + nj2 * 16 + bRowL;
                uint32_t seg = (uint32_t)((ks * 2 + bSegH) ^ (r & 7));
                ldsm_x4(b, bBase + (uint32_t)(r * 128) + (seg << 4));
#pragma unroll
                for (int mi = 0; mi < 4; mi++) {
                    mma16816(acc[mi][nj2 * 2 + 0], a[mi], b[0], b[1]);
                    mma16816(acc[mi][nj2 * 2 + 1], a[mi], b[2], b[3]);
                }
            }
        }

        if (hasNext) {
            CP_WAIT0();
            __syncthreads();
            buf ^= 1;
        }
    }

    // ---- epilogue: +bias, store (rows lane/4, +8; cols 2(lane%4)) ----
    const int rBase0 = rowBase + wr * 64 + (lane >> 2);
    const int cBase  = colBase + wc * 64 + ((lane & 3) << 1);
#pragma unroll
    for (int mi = 0; mi < 4; mi++) {
        int r0 = rBase0 + mi * 16;
        int r1 = r0 + 8;
#pragma unroll
        for (int nj = 0; nj < 8; nj++) {
            int col = cBase + nj * 8;
            float2 b2 = *(const float2*)&biascat[col];
            if (r0 < M) {
                float2 o = make_float2(acc[mi][nj][0] + b2.x, acc[mi][nj][1] + b2.y);
                *(float2*)&C[(size_t)r0 * Ncat + col] = o;
            }
            if (r1 < M) {
                float2 o = make_float2(acc[mi][nj][2] + b2.x, acc[mi][nj][3] + b2.y);
                *(float2*)&C[(size_t)r1 * Ncat + col] = o;
            }
        }
    }
}

// ----------------------------------------------------------------------------
// Edge kernel on concatenated layout: K at +0, Q at +D, V at +2D, H at +3D.
//   m = sigmoid(K[dst]+Q[src]) * V[src];  H[dst] += m (red.global.v4)
// ----------------------------------------------------------------------------
__global__ void edge_gate(const void* __restrict__ ei_raw,
                          float* __restrict__ cat,
                          int E, int D, int stride, int cshift)
{
    long long idx = (long long)blockIdx.x * blockDim.x + threadIdx.x;
    long long total = (long long)E << cshift;
    if (idx >= total) return;
    int e = (int)(idx >> cshift);
    int c = ((int)idx & ((1 << cshift) - 1)) << 2;

    int src, dst;
    if (g_is64) {
        const long long* ei = (const long long*)ei_raw;
        src = (int)ei[e];
        dst = (int)ei[E + e];
    } else {
        const int* ei = (const int*)ei_raw;
        src = ei[e];
        dst = ei[E + e];
    }

    const float4 k = *(const float4*)&cat[(size_t)dst * stride + c];
    const float4 q = *(const float4*)&cat[(size_t)src * stride + D + c];
    const float4 v = *(const float4*)&cat[(size_t)src * stride + 2 * D + c];

    float4 m;
    m.x = v.x / (1.f + __expf(-(k.x + q.x)));
    m.y = v.y / (1.f + __expf(-(k.y + q.y)));
    m.z = v.z / (1.f + __expf(-(k.z + q.z)));
    m.w = v.w / (1.f + __expf(-(k.w + q.w)));

    float* addr = &cat[(size_t)dst * stride + 3 * D + c];
    asm volatile("red.global.add.v4.f32 [%0], {%1,%2,%3,%4};"
                 :: "l"(addr), "f"(m.x), "f"(m.y), "f"(m.z), "f"(m.w)
                 : "memory");
}

// ----------------------------------------------------------------------------
// Row softmax over 64 cols (strided source): one warp per row.
// ----------------------------------------------------------------------------
__global__ void softmax64(const float* __restrict__ H, int stride, int off,
                          float* __restrict__ out, int M)
{
    int warp = threadIdx.x >> 5;
    int lane = threadIdx.x & 31;
    int row  = blockIdx.x * (blockDim.x >> 5) + warp;
    if (row >= M) return;
    float a = H[(size_t)row * stride + off + lane];
    float b = H[(size_t)row * stride + off + 32 + lane];
    float mx = fmaxf(a, b);
#pragma unroll
    for (int o = 16; o > 0; o >>= 1) mx = fmaxf(mx, __shfl_xor_sync(0xffffffffu, mx, o));
    float ea = __expf(a - mx);
    float eb = __expf(b - mx);
    float s  = ea + eb;
#pragma unroll
    for (int o = 16; o > 0; o >>= 1) s += __shfl_xor_sync(0xffffffffu, s, o);
    float inv = 1.f / s;
    out[row * 64 + lane]      = ea * inv;
    out[row * 64 + 32 + lane] = eb * inv;
}

// ----------------------------------------------------------------------------
extern "C" void kernel_launch(void* const* d_in, const int* in_sizes, int n_in,
                              void* d_out, int out_size)
{
    const float* x  = (const float*)d_in[0];
    const void*  ei = d_in[1];
    const int Nn = in_sizes[0] / 256;
    const int E  = in_sizes[1] / 2;

    float *pCat, *pBias;
    __nv_bfloat16 *pAhi, *pAlo, *pWhi, *pWlo;
    cudaGetSymbolAddress((void**)&pCat,  g_cat);
    cudaGetSymbolAddress((void**)&pAhi,  g_Ahi);
    cudaGetSymbolAddress((void**)&pAlo,  g_Alo);
    cudaGetSymbolAddress((void**)&pWhi,  g_Whi);
    cudaGetSymbolAddress((void**)&pWlo,  g_Wlo);
    cudaGetSymbolAddress((void**)&pBias, g_bias);

    const float* w[26];
    for (int i = 2; i < 26; i++) w[i] = (const float*)d_in[i];

    const int gm = (Nn + 127) / 128;   // 157 M-tiles
    const int SMEM = 2 * ABUF_BYTES;   // 64 KB
    cudaFuncSetAttribute(gemm_mma, cudaFuncAttributeMaxDynamicSharedMemorySize, SMEM);

    detect_i64<<<1, 256>>>((const unsigned int*)ei);

    // ---- layer 1: K=256, D=256, Ncat=1024 ----
    conv_w<<<(1024 * 256 + 255) / 256, 256>>>(
        w[2], w[4], w[6], w[20], w[3], w[5], w[7], w[21],
        pWhi, pWlo, pBias, 256, 256);
    conv_a<<<(Nn * 256 + 255) / 256, 256>>>(x, 256, 0, pAhi, pAlo, Nn, 256);
    gemm_mma<<<dim3(gm, 8), 128, SMEM>>>(pAhi, pAlo, pWhi, pWlo, pBias, pCat, Nn, 256, 1024);
    {
        long long tot = (long long)E * 64;
        edge_gate<<<(unsigned)((tot + 255) / 256), 256>>>(ei, pCat, E, 256, 1024, 6);
    }

    // ---- layer 2: K=256, D=128, Ncat=512 ----
    conv_w<<<(512 * 256 + 255) / 256, 256>>>(
        w[8], w[10], w[12], w[22], w[9], w[11], w[13], w[23],
        pWhi, pWlo, pBias, 256, 128);
    conv_a<<<(Nn * 256 + 255) / 256, 256>>>(pCat, 1024, 768, pAhi, pAlo, Nn, 256);
    gemm_mma<<<dim3(gm, 4), 128, SMEM>>>(pAhi, pAlo, pWhi, pWlo, pBias, pCat, Nn, 256, 512);
    {
        long long tot = (long long)E * 32;
        edge_gate<<<(unsigned)((tot + 255) / 256), 256>>>(ei, pCat, E, 128, 512, 5);
    }

    // ---- layer 3: K=128, D=64, Ncat=256 ----
    conv_w<<<(256 * 128 + 255) / 256, 256>>>(
        w[14], w[16], w[18], w[24], w[15], w[17], w[19], w[25],
        pWhi, pWlo, pBias, 128, 64);
    conv_a<<<(Nn * 128 + 255) / 256, 256>>>(pCat, 512, 384, pAhi, pAlo, Nn, 128);
    gemm_mma<<<dim3(gm, 2), 128, SMEM>>>(pAhi, pAlo, pWhi, pWlo, pBias, pCat, Nn, 128, 256);
    {
        long long tot = (long long)E * 16;
        edge_gate<<<(unsigned)((tot + 255) / 256), 256>>>(ei, pCat, E, 64, 256, 4);
    }

    softmax64<<<(Nn + 7) / 8, 256>>>(pCat, 256, 192, (float*)d_out, Nn);
}